// round 6
// baseline (speedup 1.0000x reference)
#include <cuda_runtime.h>
#include <cuda_bf16.h>

// activation (N=32, C=16, H=224, W=224) fp32.
// c0-1 identity, c2-3 1x1 relu, c4-7 2x2, c8-11 4x4, c12-15 3x3.
#define HW4 12544   // float4 per image-channel
#define W4  56      // float4 per row
#define H_  224
#define Q_  3136    // HW4/4

// Per-image thread units (heavy-first), R4 layout:
//   [0,     5700) : 3x3 units   (4ch * 1425, 9 f4, low-reg two-pass)
//   [5700, 18244) : 4x4 units   (4ch * 3136, 4 rows x 1 f4)
//   [18244,30788) : 2x2 units   (4ch * 3136, 4 rows x 1 f4)
//   [30788,43332) : elementwise (4ch * 3136, 4 strided f4)
#define SEG_C 5700
#define SEG_B 18244
#define SEG_A 30788
#define PER_N 43332
#define TOTAL (32 * PER_N)   // 1,386,624

// Forced global load (defeats CSE with the first-pass loads; hits L1).
__device__ __forceinline__ float4 ldg_force(const float4* p) {
    float4 v;
    asm volatile("ld.global.ca.v4.f32 {%0,%1,%2,%3}, [%4];"
                 : "=f"(v.x), "=f"(v.y), "=f"(v.z), "=f"(v.w) : "l"(p));
    return v;
}

__global__ __launch_bounds__(256, 6) void block_relu_fused(
    const float4* __restrict__ in, float4* __restrict__ out)
{
    int i = blockIdx.x * 256 + threadIdx.x;
    if (i >= TOTAL) return;
    int n = i / PER_N;
    int u = i - n * PER_N;
    const size_t nbase = (size_t)n * 16 * HW4;

    if (u >= SEG_A) {
        // ---- c0-3: identity / elementwise relu, 4 strided float4 ----
        int t    = u - SEG_A;
        int c    = t / Q_;
        int off0 = t - c * Q_;
        size_t g = nbase + (size_t)c * HW4 + off0;
        float4 v0 = in[g];
        float4 v1 = in[g + Q_];
        float4 v2 = in[g + 2 * Q_];
        float4 v3 = in[g + 3 * Q_];
        if (c >= 2) {
            v0.x = fmaxf(v0.x, 0.f); v0.y = fmaxf(v0.y, 0.f); v0.z = fmaxf(v0.z, 0.f); v0.w = fmaxf(v0.w, 0.f);
            v1.x = fmaxf(v1.x, 0.f); v1.y = fmaxf(v1.y, 0.f); v1.z = fmaxf(v1.z, 0.f); v1.w = fmaxf(v1.w, 0.f);
            v2.x = fmaxf(v2.x, 0.f); v2.y = fmaxf(v2.y, 0.f); v2.z = fmaxf(v2.z, 0.f); v2.w = fmaxf(v2.w, 0.f);
            v3.x = fmaxf(v3.x, 0.f); v3.y = fmaxf(v3.y, 0.f); v3.z = fmaxf(v3.z, 0.f); v3.w = fmaxf(v3.w, 0.f);
        }
        out[g]          = v0;
        out[g + Q_]     = v1;
        out[g + 2 * Q_] = v2;
        out[g + 3 * Q_] = v3;
    } else if (u >= SEG_C) {
        // ---- c4-11: 4 rows x 1 float4 per thread ----
        bool is2x2 = (u >= SEG_B);
        int t  = u - (is2x2 ? SEG_B : SEG_C);
        int c  = (is2x2 ? 4 : 8) + t / Q_;
        int v  = t % Q_;
        int rq = v / W4;
        int f4 = v - rq * W4;
        size_t i0 = nbase + (size_t)c * HW4 + (size_t)(4 * rq) * W4 + f4;

        float4 r0 = in[i0];
        float4 r1 = in[i0 + W4];
        float4 r2 = in[i0 + 2 * W4];
        float4 r3 = in[i0 + 3 * W4];

        if (is2x2) {
            float tx = r0.x + r1.x, ty = r0.y + r1.y, tz = r0.z + r1.z, tw = r0.w + r1.w;
            float bx = r2.x + r3.x, by = r2.y + r3.y, bz = r2.z + r3.z, bw = r2.w + r3.w;
            float mTL = ((tx + ty) >= 0.f) ? 1.f : 0.f;
            float mTR = ((tz + tw) >= 0.f) ? 1.f : 0.f;
            float mBL = ((bx + by) >= 0.f) ? 1.f : 0.f;
            float mBR = ((bz + bw) >= 0.f) ? 1.f : 0.f;
            r0.x *= mTL; r0.y *= mTL; r0.z *= mTR; r0.w *= mTR;
            r1.x *= mTL; r1.y *= mTL; r1.z *= mTR; r1.w *= mTR;
            r2.x *= mBL; r2.y *= mBL; r2.z *= mBR; r2.w *= mBR;
            r3.x *= mBL; r3.y *= mBL; r3.z *= mBR; r3.w *= mBR;
        } else {
            float cs0 = r0.x + r1.x + r2.x + r3.x;
            float cs1 = r0.y + r1.y + r2.y + r3.y;
            float cs2 = r0.z + r1.z + r2.z + r3.z;
            float cs3 = r0.w + r1.w + r2.w + r3.w;
            float m = ((cs0 + cs1 + cs2 + cs3) >= 0.f) ? 1.f : 0.f;
            r0.x *= m; r0.y *= m; r0.z *= m; r0.w *= m;
            r1.x *= m; r1.y *= m; r1.z *= m; r1.w *= m;
            r2.x *= m; r2.y *= m; r2.z *= m; r2.w *= m;
            r3.x *= m; r3.y *= m; r3.z *= m; r3.w *= m;
        }
        out[i0]          = r0;
        out[i0 + W4]     = r1;
        out[i0 + 2 * W4] = r2;
        out[i0 + 3 * W4] = r3;
    } else {
        // ---- c12-15: 3x3 blocks, 4 blocks per thread, low-register two-pass ----
        int c  = 12 + u / 1425;
        int v  = u % 1425;
        int br = v / 19;              // block-row 0..74
        int s  = v - br * 19;         // 12-col strip 0..18
        int r0 = br * 3;
        size_t base = nbase + (size_t)c * HW4;

        // Pass 1: accumulate 12 column sums row by row (3 f4 live at a time).
        float cs[12];
        #pragma unroll
        for (int q = 0; q < 12; q++) cs[q] = 0.f;

        #pragma unroll
        for (int r = 0; r < 3; r++) {
            int rr = r0 + r;
            if (rr < H_) {
                #pragma unroll
                for (int k = 0; k < 3; k++) {
                    int fc = s * 3 + k;
                    if (fc < W4) {
                        float4 t = in[base + (size_t)rr * W4 + fc];
                        cs[4 * k + 0] += t.x;
                        cs[4 * k + 1] += t.y;
                        cs[4 * k + 2] += t.z;
                        cs[4 * k + 3] += t.w;
                    }
                }
            }
        }
        float m[4];
        #pragma unroll
        for (int g = 0; g < 4; g++)
            m[g] = ((cs[3 * g] + cs[3 * g + 1] + cs[3 * g + 2]) >= 0.f) ? 1.f : 0.f;

        // Pass 2: reload (L1-hot), scale, store — 3 f4 live.
        #pragma unroll
        for (int r = 0; r < 3; r++) {
            int rr = r0 + r;
            if (rr >= H_) break;
            #pragma unroll
            for (int k = 0; k < 3; k++) {
                int fc = s * 3 + k;
                if (fc < W4) {
                    float4 t = ldg_force(in + base + (size_t)rr * W4 + fc);
                    int L = 4 * k;
                    t.x *= m[(L + 0) / 3];
                    t.y *= m[(L + 1) / 3];
                    t.z *= m[(L + 2) / 3];
                    t.w *= m[(L + 3) / 3];
                    out[base + (size_t)rr * W4 + fc] = t;
                }
            }
        }
    }
}

extern "C" void kernel_launch(void* const* d_in, const int* in_sizes, int n_in,
                              void* d_out, int out_size)
{
    const float4* in  = (const float4*)d_in[0];
    float4*       out = (float4*)d_out;
    block_relu_fused<<<(TOTAL + 255) / 256, 256>>>(in, out);  // 5417 CTAs
}

// round 7
// speedup vs baseline: 1.0437x; 1.0437x over previous
#include <cuda_runtime.h>
#include <cuda_bf16.h>

// activation (N=32, C=16, H=224, W=224) fp32.
// c0-1 identity, c2-3 1x1 relu, c4-7 2x2, c8-11 4x4, c12-15 3x3.
#define HW4 12544   // float4 per image-channel
#define W4  56      // float4 per row
#define H_  224
#define Q_  3136    // HW4/4

// Per-image thread units (heavy-first), R4 layout:
//   [0,     5700) : 3x3 units   (4ch * 1425, 9 f4 single-pass)
//   [5700, 18244) : 4x4 units   (4ch * 3136, 4 rows x 1 f4)
//   [18244,30788) : 2x2 units   (4ch * 3136, 4 rows x 1 f4)
//   [30788,43332) : elementwise (4ch * 3136, 4 rows x 1 f4)
#define SEG_C 5700
#define SEG_B 18244
#define SEG_A 30788
#define PER_N 43332
#define TOTAL (32 * PER_N)   // 1,386,624

__global__ __launch_bounds__(256, 5) void block_relu_fused(
    const float4* __restrict__ in, float4* __restrict__ out)
{
    int i = blockIdx.x * 256 + threadIdx.x;
    if (i >= TOTAL) return;
    int n = i / PER_N;
    int u = i - n * PER_N;
    const size_t nbase = (size_t)n * 16 * HW4;

    if (u >= SEG_A) {
        // ---- c0-3: identity / elementwise relu, 4 consecutive rows x 1 f4 ----
        int t  = u - SEG_A;
        int c  = t / Q_;
        int v  = t - c * Q_;
        int rq = v / W4;
        int f4 = v - rq * W4;
        size_t g = nbase + (size_t)c * HW4 + (size_t)(4 * rq) * W4 + f4;
        float4 v0 = in[g];
        float4 v1 = in[g + W4];
        float4 v2 = in[g + 2 * W4];
        float4 v3 = in[g + 3 * W4];
        if (c >= 2) {
            v0.x = fmaxf(v0.x, 0.f); v0.y = fmaxf(v0.y, 0.f); v0.z = fmaxf(v0.z, 0.f); v0.w = fmaxf(v0.w, 0.f);
            v1.x = fmaxf(v1.x, 0.f); v1.y = fmaxf(v1.y, 0.f); v1.z = fmaxf(v1.z, 0.f); v1.w = fmaxf(v1.w, 0.f);
            v2.x = fmaxf(v2.x, 0.f); v2.y = fmaxf(v2.y, 0.f); v2.z = fmaxf(v2.z, 0.f); v2.w = fmaxf(v2.w, 0.f);
            v3.x = fmaxf(v3.x, 0.f); v3.y = fmaxf(v3.y, 0.f); v3.z = fmaxf(v3.z, 0.f); v3.w = fmaxf(v3.w, 0.f);
        }
        out[g]          = v0;
        out[g + W4]     = v1;
        out[g + 2 * W4] = v2;
        out[g + 3 * W4] = v3;
    } else if (u >= SEG_C) {
        // ---- c4-11: 4 rows x 1 float4 per thread ----
        bool is2x2 = (u >= SEG_B);
        int t  = u - (is2x2 ? SEG_B : SEG_C);
        int c  = (is2x2 ? 4 : 8) + t / Q_;
        int v  = t % Q_;
        int rq = v / W4;
        int f4 = v - rq * W4;
        size_t i0 = nbase + (size_t)c * HW4 + (size_t)(4 * rq) * W4 + f4;

        float4 r0 = in[i0];
        float4 r1 = in[i0 + W4];
        float4 r2 = in[i0 + 2 * W4];
        float4 r3 = in[i0 + 3 * W4];

        if (is2x2) {
            float tx = r0.x + r1.x, ty = r0.y + r1.y, tz = r0.z + r1.z, tw = r0.w + r1.w;
            float bx = r2.x + r3.x, by = r2.y + r3.y, bz = r2.z + r3.z, bw = r2.w + r3.w;
            float mTL = ((tx + ty) >= 0.f) ? 1.f : 0.f;
            float mTR = ((tz + tw) >= 0.f) ? 1.f : 0.f;
            float mBL = ((bx + by) >= 0.f) ? 1.f : 0.f;
            float mBR = ((bz + bw) >= 0.f) ? 1.f : 0.f;
            r0.x *= mTL; r0.y *= mTL; r0.z *= mTR; r0.w *= mTR;
            r1.x *= mTL; r1.y *= mTL; r1.z *= mTR; r1.w *= mTR;
            r2.x *= mBL; r2.y *= mBL; r2.z *= mBR; r2.w *= mBR;
            r3.x *= mBL; r3.y *= mBL; r3.z *= mBR; r3.w *= mBR;
        } else {
            float cs0 = r0.x + r1.x + r2.x + r3.x;
            float cs1 = r0.y + r1.y + r2.y + r3.y;
            float cs2 = r0.z + r1.z + r2.z + r3.z;
            float cs3 = r0.w + r1.w + r2.w + r3.w;
            float m = ((cs0 + cs1 + cs2 + cs3) >= 0.f) ? 1.f : 0.f;
            r0.x *= m; r0.y *= m; r0.z *= m; r0.w *= m;
            r1.x *= m; r1.y *= m; r1.z *= m; r1.w *= m;
            r2.x *= m; r2.y *= m; r2.z *= m; r2.w *= m;
            r3.x *= m; r3.y *= m; r3.z *= m; r3.w *= m;
        }
        out[i0]          = r0;
        out[i0 + W4]     = r1;
        out[i0 + 2 * W4] = r2;
        out[i0 + 3 * W4] = r3;
    } else {
        // ---- c12-15: 3x3 blocks, four blocks per thread (3 rows x 12 cols), single pass ----
        int c  = 12 + u / 1425;
        int v  = u % 1425;
        int br = v / 19;              // block-row 0..74
        int s  = v - br * 19;         // 12-col strip 0..18
        int r0 = br * 3;
        size_t base = nbase + (size_t)c * HW4;

        float4 val[3][3];
        #pragma unroll
        for (int r = 0; r < 3; r++) {
            int rr = r0 + r;
            bool rv = rr < H_;
            #pragma unroll
            for (int k = 0; k < 3; k++) {
                int fc = s * 3 + k;
                if (rv && fc < W4)
                    val[r][k] = in[base + (size_t)rr * W4 + fc];
                else
                    val[r][k] = make_float4(0.f, 0.f, 0.f, 0.f);
            }
        }

        float cs[12];
        #pragma unroll
        for (int k = 0; k < 3; k++) {
            cs[4 * k + 0] = val[0][k].x + val[1][k].x + val[2][k].x;
            cs[4 * k + 1] = val[0][k].y + val[1][k].y + val[2][k].y;
            cs[4 * k + 2] = val[0][k].z + val[1][k].z + val[2][k].z;
            cs[4 * k + 3] = val[0][k].w + val[1][k].w + val[2][k].w;
        }
        float m[4];
        #pragma unroll
        for (int g = 0; g < 4; g++)
            m[g] = ((cs[3 * g] + cs[3 * g + 1] + cs[3 * g + 2]) >= 0.f) ? 1.f : 0.f;

        #pragma unroll
        for (int r = 0; r < 3; r++) {
            int rr = r0 + r;
            if (rr >= H_) break;
            #pragma unroll
            for (int k = 0; k < 3; k++) {
                int fc = s * 3 + k;
                if (fc < W4) {
                    float4 tv = val[r][k];
                    int L = 4 * k;
                    tv.x *= m[(L + 0) / 3];
                    tv.y *= m[(L + 1) / 3];
                    tv.z *= m[(L + 2) / 3];
                    tv.w *= m[(L + 3) / 3];
                    out[base + (size_t)rr * W4 + fc] = tv;
                }
            }
        }
    }
}

extern "C" void kernel_launch(void* const* d_in, const int* in_sizes, int n_in,
                              void* d_out, int out_size)
{
    const float4* in  = (const float4*)d_in[0];
    float4*       out = (float4*)d_out;
    block_relu_fused<<<(TOTAL + 255) / 256, 256>>>(in, out);  // 5417 CTAs
}

// round 8
// speedup vs baseline: 1.1023x; 1.0561x over previous
#include <cuda_runtime.h>
#include <cuda_bf16.h>

// activation (N=32, C=16, H=224, W=224) fp32.
// c0-1 identity, c2-3 1x1 relu, c4-7 2x2, c8-11 4x4, c12-15 3x3.
#define HW4 12544   // float4 per image-channel
#define W4  56      // float4 per row
#define H_  224
#define Q_  3136    // HW4/4
#define Q8  1568    // HW4/8

// Per-image thread units (heavy-first):
//   [0,     5700) : 3x3 units   (4ch * 1425, 9 f4)              -- unchanged from R4
//   [5700, 11972) : 4x4 units   (4ch * 1568: 8 rows x 1 f4)     -- MLP 8, full density
//   [11972, 18244): 2x2 units   (4ch * 1568: 8 rows x 1 f4)     -- MLP 8, full density
//   [18244, 30788): elementwise (4ch * 3136: 4 f4, Q_ stride)   -- unchanged from R4
#define SEG_C 5700
#define SEG_B 11972
#define SEG_A 18244
#define PER_N 30788
#define TOTAL (32 * PER_N)   // 985,216

__global__ __launch_bounds__(256) void block_relu_fused(
    const float4* __restrict__ in, float4* __restrict__ out)
{
    int i = blockIdx.x * 256 + threadIdx.x;
    if (i >= TOTAL) return;
    int n = i / PER_N;
    int u = i - n * PER_N;
    const size_t nbase = (size_t)n * 16 * HW4;

    if (u >= SEG_A) {
        // ---- c0-3: identity / elementwise relu, 4 strided float4 (exact R4) ----
        int t    = u - SEG_A;
        int c    = t / Q_;
        int off0 = t - c * Q_;
        size_t g = nbase + (size_t)c * HW4 + off0;
        float4 v0 = in[g];
        float4 v1 = in[g + Q_];
        float4 v2 = in[g + 2 * Q_];
        float4 v3 = in[g + 3 * Q_];
        if (c >= 2) {
            v0.x = fmaxf(v0.x, 0.f); v0.y = fmaxf(v0.y, 0.f); v0.z = fmaxf(v0.z, 0.f); v0.w = fmaxf(v0.w, 0.f);
            v1.x = fmaxf(v1.x, 0.f); v1.y = fmaxf(v1.y, 0.f); v1.z = fmaxf(v1.z, 0.f); v1.w = fmaxf(v1.w, 0.f);
            v2.x = fmaxf(v2.x, 0.f); v2.y = fmaxf(v2.y, 0.f); v2.z = fmaxf(v2.z, 0.f); v2.w = fmaxf(v2.w, 0.f);
            v3.x = fmaxf(v3.x, 0.f); v3.y = fmaxf(v3.y, 0.f); v3.z = fmaxf(v3.z, 0.f); v3.w = fmaxf(v3.w, 0.f);
        }
        out[g]          = v0;
        out[g + Q_]     = v1;
        out[g + 2 * Q_] = v2;
        out[g + 3 * Q_] = v3;
    } else if (u >= SEG_C) {
        // ---- c4-11: 8 rows x 1 float4 per thread, full-density warp access ----
        bool is2x2 = (u >= SEG_B);
        int t  = u - (is2x2 ? SEG_B : SEG_C);
        int c  = (is2x2 ? 4 : 8) + t / Q8;
        int v  = t % Q8;
        int rq = v / W4;                   // 8-row group 0..27
        int f4 = v - rq * W4;
        size_t i0 = nbase + (size_t)c * HW4 + (size_t)(8 * rq) * W4 + f4;

        float4 r[8];
        #pragma unroll
        for (int j = 0; j < 8; j++) r[j] = in[i0 + (size_t)j * W4];

        if (is2x2) {
            // four vertical 2-row pairs, each with left (xy) and right (zw) masks
            #pragma unroll
            for (int p = 0; p < 4; p++) {
                float4 a = r[2 * p], b = r[2 * p + 1];
                float sx = a.x + b.x, sy = a.y + b.y, sz = a.z + b.z, sw = a.w + b.w;
                float mL = ((sx + sy) >= 0.f) ? 1.f : 0.f;
                float mR = ((sz + sw) >= 0.f) ? 1.f : 0.f;
                a.x *= mL; a.y *= mL; a.z *= mR; a.w *= mR;
                b.x *= mL; b.y *= mL; b.z *= mR; b.w *= mR;
                r[2 * p] = a; r[2 * p + 1] = b;
            }
        } else {
            // two vertical 4-row blocks, one mask each
            #pragma unroll
            for (int p = 0; p < 2; p++) {
                float cs0 = r[4*p].x + r[4*p+1].x + r[4*p+2].x + r[4*p+3].x;
                float cs1 = r[4*p].y + r[4*p+1].y + r[4*p+2].y + r[4*p+3].y;
                float cs2 = r[4*p].z + r[4*p+1].z + r[4*p+2].z + r[4*p+3].z;
                float cs3 = r[4*p].w + r[4*p+1].w + r[4*p+2].w + r[4*p+3].w;
                float m = ((cs0 + cs1 + cs2 + cs3) >= 0.f) ? 1.f : 0.f;
                #pragma unroll
                for (int j = 0; j < 4; j++) {
                    r[4*p+j].x *= m; r[4*p+j].y *= m; r[4*p+j].z *= m; r[4*p+j].w *= m;
                }
            }
        }
        #pragma unroll
        for (int j = 0; j < 8; j++) out[i0 + (size_t)j * W4] = r[j];
    } else {
        // ---- c12-15: 3x3 blocks, four blocks per thread (exact R4) ----
        int c  = 12 + u / 1425;
        int v  = u % 1425;
        int br = v / 19;              // block-row 0..74
        int s  = v - br * 19;         // 12-col strip 0..18
        int r0 = br * 3;
        size_t base = nbase + (size_t)c * HW4;

        float4 val[3][3];
        #pragma unroll
        for (int r = 0; r < 3; r++) {
            int rr = r0 + r;
            bool rv = rr < H_;
            #pragma unroll
            for (int k = 0; k < 3; k++) {
                int fc = s * 3 + k;
                if (rv && fc < W4)
                    val[r][k] = in[base + (size_t)rr * W4 + fc];
                else
                    val[r][k] = make_float4(0.f, 0.f, 0.f, 0.f);
            }
        }

        float cs[12];
        #pragma unroll
        for (int k = 0; k < 3; k++) {
            cs[4 * k + 0] = val[0][k].x + val[1][k].x + val[2][k].x;
            cs[4 * k + 1] = val[0][k].y + val[1][k].y + val[2][k].y;
            cs[4 * k + 2] = val[0][k].z + val[1][k].z + val[2][k].z;
            cs[4 * k + 3] = val[0][k].w + val[1][k].w + val[2][k].w;
        }
        float m[4];
        #pragma unroll
        for (int g = 0; g < 4; g++)
            m[g] = ((cs[3 * g] + cs[3 * g + 1] + cs[3 * g + 2]) >= 0.f) ? 1.f : 0.f;

        #pragma unroll
        for (int r = 0; r < 3; r++) {
            int rr = r0 + r;
            if (rr >= H_) break;
            #pragma unroll
            for (int k = 0; k < 3; k++) {
                int fc = s * 3 + k;
                if (fc < W4) {
                    float4 tv = val[r][k];
                    int L = 4 * k;
                    tv.x *= m[(L + 0) / 3];
                    tv.y *= m[(L + 1) / 3];
                    tv.z *= m[(L + 2) / 3];
                    tv.w *= m[(L + 3) / 3];
                    out[base + (size_t)rr * W4 + fc] = tv;
                }
            }
        }
    }
}

extern "C" void kernel_launch(void* const* d_in, const int* in_sizes, int n_in,
                              void* d_out, int out_size)
{
    const float4* in  = (const float4*)d_in[0];
    float4*       out = (float4*)d_out;
    block_relu_fused<<<(TOTAL + 255) / 256, 256>>>(in, out);  // 3849 CTAs
}